// round 7
// baseline (speedup 1.0000x reference)
#include <cuda_runtime.h>
#include <cuda_bf16.h>
#include <math.h>

#define BB   8
#define QQ   2048
#define KK2  2048
#define FF   512
#define FVV  512
#define NTHREADS 256

// ---------------- scratch (device globals; no runtime allocation) ----------------
// bf16 A-blob (64x64): [ks4][mf4][lane32][4 b32] ; regs: r0=(g,2t..),r1=(g+8,2t..),r2=(g,2t+8..),r3=(g+8,2t+8..)
// bf16 B-blob (64x64): [ks4][nf8][lane32][2 b32] ; r0=(k=2t..,n=g), r1=(k=2t+8..,n=g)
// tf32 B-blob (64x64): [ks8][nf8][lane32][2 b32] ; r0=(k=t,n=g), r1=(k=t+4,n=g)
__device__ __align__(16) unsigned g_Qpb[4194304];     // (b, qt32, ft8) bf16 A-blobs  16.8MB
__device__ __align__(16) unsigned g_Kpb[4194304];     // (b, kt32, ft8) bf16 B-blobs  16.8MB
__device__ __align__(16) float    g_Vp [8388608];     // (b, fvt8, kt32) tf32 B-blobs 33.5MB
__device__ __align__(16) __nv_bfloat16 g_E[33554432]; // exp(logits) row-major        67MB
__device__ float g_linv[BB*QQ];
__device__ int   g_mask_is_int32;

// ---------------- helpers ----------------
__device__ __forceinline__ unsigned to_tf32(float f){
    unsigned u; asm("cvt.rna.tf32.f32 %0, %1;" : "=r"(u) : "f"(f)); return u;
}
__device__ __forceinline__ void mma_tf32(float c[4], const unsigned* a, const unsigned* b){
    asm volatile("mma.sync.aligned.m16n8k8.row.col.f32.tf32.tf32.f32 "
        "{%0,%1,%2,%3}, {%4,%5,%6,%7}, {%8,%9}, {%0,%1,%2,%3};"
        : "+f"(c[0]), "+f"(c[1]), "+f"(c[2]), "+f"(c[3])
        : "r"(a[0]), "r"(a[1]), "r"(a[2]), "r"(a[3]), "r"(b[0]), "r"(b[1]));
}
__device__ __forceinline__ void mma_bf16(float c[4], const unsigned* a, const unsigned* b){
    asm volatile("mma.sync.aligned.m16n8k16.row.col.f32.bf16.bf16.f32 "
        "{%0,%1,%2,%3}, {%4,%5,%6,%7}, {%8,%9}, {%0,%1,%2,%3};"
        : "+f"(c[0]), "+f"(c[1]), "+f"(c[2]), "+f"(c[3])
        : "r"(a[0]), "r"(a[1]), "r"(a[2]), "r"(a[3]), "r"(b[0]), "r"(b[1]));
}
// exp on the FMA pipe: 2^(x*log2e), deg-5 poly (rel err ~2e-7 for |x| < 15)
__device__ __forceinline__ float fexp(float x){
    float t = x * 1.4426950408889634f;
    float r = rintf(t);
    float f = t - r;
    float p = 1.3333558146428443e-3f;
    p = fmaf(p, f, 9.618129107628477e-3f);
    p = fmaf(p, f, 5.550410866482158e-2f);
    p = fmaf(p, f, 2.402265069591007e-1f);
    p = fmaf(p, f, 6.931471805599453e-1f);
    p = fmaf(p, f, 1.0f);
    return __int_as_float(((int)r + 127) << 23) * p;
}
// rsqrt on FMA pipe, 2 Newton steps (~1e-6 rel)
__device__ __forceinline__ float frsqrt2(float x){
    float y = __int_as_float(0x5f3759df - (__float_as_int(x) >> 1));
    y = y * (1.5f - 0.5f * x * y * y);
    y = y * (1.5f - 0.5f * x * y * y);
    return y;
}

// ---------------- mask dtype probe ----------------
__global__ void detect_mask_kernel(const unsigned char* am){
    unsigned nz = 0;
    #pragma unroll 8
    for (int i = 0; i < 1024; i++) nz |= am[4*i+1] | am[4*i+2] | am[4*i+3];
    g_mask_is_int32 = (nz == 0u) ? 1 : 0;
}

// ---------------- prep Q -> bf16 A-fragment blobs ----------------
__global__ void __launch_bounds__(NTHREADS) prep_qb_kernel(const float* __restrict__ q){
    int w = blockIdx.x * 8 + (threadIdx.x >> 5);
    int lane = threadIdx.x & 31, g = lane >> 2, t = lane & 3;
    int mf = w & 3, ks = (w>>2)&3, ft = (w>>4)&7, qt = (w>>7)&31, b = w>>12;
    unsigned rr[4];
    #pragma unroll
    for (int rh = 0; rh < 2; rh++){
        int row = qt*64 + mf*16 + g + 8*rh;
        const float* qp = q + ((size_t)(b*QQ + row))*FF + ft*64 + ks*16 + 2*t;
        float2 x0 = *(const float2*)qp;
        float2 x1 = *(const float2*)(qp + 8);
        __nv_bfloat162 h0 = __floats2bfloat162_rn(x0.x, x0.y);
        __nv_bfloat162 h1 = __floats2bfloat162_rn(x1.x, x1.y);
        rr[rh]   = *(unsigned*)&h0;
        rr[rh+2] = *(unsigned*)&h1;
    }
    size_t blob = ((size_t)((b*32 + qt)*8 + ft))*2048;
    *(uint4*)(g_Qpb + blob + ((ks*4 + mf)*32 + lane)*4) = make_uint4(rr[0],rr[1],rr[2],rr[3]);
}

// ---------------- prep K -> bf16 B-fragment blobs ----------------
__global__ void __launch_bounds__(NTHREADS) prep_kb_kernel(const float* __restrict__ k){
    int w = blockIdx.x * 8 + (threadIdx.x >> 5);
    int lane = threadIdx.x & 31, g = lane >> 2, t = lane & 3;
    int nf = w & 7, ks = (w>>3)&3, ft = (w>>5)&7, kt = (w>>8)&31, b = w>>13;
    int n = kt*64 + nf*8 + g;
    const float* kp = k + ((size_t)(b*KK2 + n))*FF + ft*64 + ks*16 + 2*t;
    float2 x0 = *(const float2*)kp;
    float2 x1 = *(const float2*)(kp + 8);
    __nv_bfloat162 h0 = __floats2bfloat162_rn(x0.x, x0.y);
    __nv_bfloat162 h1 = __floats2bfloat162_rn(x1.x, x1.y);
    size_t blob = ((size_t)((b*32 + kt)*8 + ft))*2048;
    *(uint2*)(g_Kpb + blob + ((ks*8 + nf)*32 + lane)*2) =
        make_uint2(*(unsigned*)&h0, *(unsigned*)&h1);
}

// ---------------- prep V -> tf32 B-fragment blobs (contraction = seq-k, n = fv) ----------------
__global__ void __launch_bounds__(NTHREADS) prep_v_kernel(const float* __restrict__ v){
    int w = blockIdx.x * 8 + (threadIdx.x >> 5);
    int lane = threadIdx.x & 31, g = lane >> 2, t = lane & 3;
    int nf = w & 7, ks = (w>>3)&7, kt = (w>>6)&31, fvt = (w>>11)&7, b = w>>14;
    unsigned rr[2];
    #pragma unroll
    for (int j = 0; j < 2; j++){
        int kk = kt*64 + ks*8 + t + 4*j;
        int fv = fvt*64 + nf*8 + g;
        rr[j] = to_tf32(v[((size_t)(b*KK2 + kk))*FVV + fv]);
    }
    size_t blob = ((size_t)((b*8 + fvt)*32 + kt))*4096;
    *(uint2*)(g_Vp + blob + ((ks*8 + nf)*32 + lane)*2) = make_uint2(rr[0], rr[1]);
}

// ---------------- pass1: S = QK^T * scale (bf16 mma); E = exp(S); linv = 1/rowsum ----------------
__global__ void __launch_bounds__(NTHREADS, 1) pass1_kernel(void){
    extern __shared__ unsigned smem_u[];
    unsigned* smQ = smem_u;                    // 16384 words = 64KB
    float* l_s = (float*)(smem_u + 16384);     // 8 warps * 64 rows

    int tid = threadIdx.x, lane = tid & 31, wc = tid >> 5;
    int g = lane >> 2, t = lane & 3;
    int b = blockIdx.x >> 5, qt = blockIdx.x & 31;
    const float SCALE = 0.044194173824159216f;  // 1/sqrt(512)

    {   // stage all 8 Q blobs for this q-tile
        const uint4* src = (const uint4*)(g_Qpb + ((size_t)((b*32 + qt)*8))*2048);
        uint4* dst = (uint4*)smQ;
        #pragma unroll
        for (int i = 0; i < 16; i++) dst[tid + 256*i] = src[tid + 256*i];
    }
    __syncthreads();

    float rsl[4][2];
    #pragma unroll
    for (int a=0;a<4;a++){ rsl[a][0]=0.f; rsl[a][1]=0.f; }

    #pragma unroll 1
    for (int kb = 0; kb < 8; kb++){
        int kt = kb*4 + (wc >> 1);
        int nb = (wc & 1) * 4;

        float C[4][4][4];
        #pragma unroll
        for (int a=0;a<4;a++)
            #pragma unroll
            for (int bb=0;bb<4;bb++)
                #pragma unroll
                for (int c=0;c<4;c++) C[a][bb][c]=0.f;

        #pragma unroll 1
        for (int ft = 0; ft < 8; ft++){
            const unsigned* As = smQ + ft*2048;
            const unsigned* Bb = g_Kpb + ((size_t)((b*32 + kt)*8 + ft))*2048;
            #pragma unroll
            for (int ks = 0; ks < 4; ks++){
                uint4 Af[4];
                #pragma unroll
                for (int mf=0; mf<4; mf++)
                    Af[mf] = *(const uint4*)(As + ((ks*4 + mf)*32 + lane)*4);
                uint2 Bf[4];
                #pragma unroll
                for (int nf=0; nf<4; nf++)
                    Bf[nf] = *(const uint2*)(Bb + ((ks*8 + nb + nf)*32 + lane)*2);
                #pragma unroll
                for (int mf=0; mf<4; mf++)
                    #pragma unroll
                    for (int nf=0; nf<4; nf++)
                        mma_bf16(C[mf][nf], (const unsigned*)&Af[mf], (const unsigned*)&Bf[nf]);
            }
        }

        // exp + E store + row-sum partials
        #pragma unroll
        for (int mf = 0; mf < 4; mf++)
            #pragma unroll
            for (int rh = 0; rh < 2; rh++){
                int row = qt*64 + mf*16 + g + 8*rh;
                float rs = 0.f;
                #pragma unroll
                for (int nf = 0; nf < 4; nf++){
                    float e0 = fexp(C[mf][nf][rh*2+0] * SCALE);
                    float e1 = fexp(C[mf][nf][rh*2+1] * SCALE);
                    rs += e0 + e1;
                    int kcol = kb*256 + wc*32 + nf*8 + 2*t;
                    size_t idx = ((size_t)(b*QQ + row))*KK2 + kcol;
                    ((__nv_bfloat162*)g_E)[idx >> 1] = __floats2bfloat162_rn(e0, e1);
                }
                rsl[mf][rh] += rs;
            }
    }

    #pragma unroll
    for (int mf = 0; mf < 4; mf++)
        #pragma unroll
        for (int rh = 0; rh < 2; rh++){
            float rs = rsl[mf][rh];
            rs += __shfl_xor_sync(0xffffffffu, rs, 1);
            rs += __shfl_xor_sync(0xffffffffu, rs, 2);
            if (t == 0) l_s[wc*64 + mf*16 + g + 8*rh] = rs;
        }
    __syncthreads();
    if (tid < 64){
        float s = 0.f;
        #pragma unroll
        for (int w = 0; w < 8; w++) s += l_s[w*64 + tid];
        g_linv[b*QQ + qt*64 + tid] = 1.0f / s;
    }
}

// ---------------- pass2 (fused, software-pipelined): W built in smem; O = W*V ----------------
// Loop body: build(kt+1) -> mma(kt) -> sync.  build LDGs issue before the mma phase,
// so DRAM latency for E/masks/coords is hidden under ~256 mma instructions.
#define WPAD 68
struct BuildIn {           // raw inputs for one 16-col slice of next W tile
    uint4 eu[2];           // 16 bf16 E values
    int   amv[16], alv[16];
    float4 ck4[8];         // 16 (x,y) coord pairs
};

__global__ void __launch_bounds__(NTHREADS, 1) pass2_kernel(
    float* __restrict__ out,
    const float* __restrict__ cq, const float* __restrict__ ck,
    const unsigned char* __restrict__ am, const unsigned char* __restrict__ al,
    const float* __restrict__ bias)
{
    extern __shared__ float smem[];   // 2 * 64*68 floats = 34816 B
    int tid = threadIdx.x, lane = tid & 31, wc = tid >> 5;
    int g = lane >> 2, t = lane & 3;
    int b = blockIdx.x >> 5, qt = blockIdx.x & 31;

    // build role: thread owns row brow (within q-tile), 16 cols at bc0 (within k-tile)
    const int brow = wc*8 + (lane >> 2);
    const int bc0  = (lane & 3) * 16;
    const float2 cqv = *(const float2*)(cq + ((size_t)(b*QQ + qt*64 + brow))*2);
    const float li   = g_linv[b*QQ + qt*64 + brow];
    const size_t erow = ((size_t)(b*QQ + qt*64 + brow))*KK2;
    const float bsc = __ldg(bias);
    const int m32 = g_mask_is_int32;

    // ---- load raw inputs for tile kt (all 16 cols up front -> max MLP) ----
    auto load_in = [&](int kt, BuildIn& in){
        int cb = kt*64 + bc0;
        in.eu[0] = *(const uint4*)(g_E + erow + cb);
        in.eu[1] = *(const uint4*)(g_E + erow + cb + 8);
        if (m32){
            const int4* ap = (const int4*)((const int*)am + erow + cb);
            const int4* lp = (const int4*)((const int*)al + erow + cb);
            #pragma unroll
            for (int i = 0; i < 4; i++){
                int4 a = ap[i], l = lp[i];
                in.amv[4*i+0]=a.x; in.amv[4*i+1]=a.y; in.amv[4*i+2]=a.z; in.amv[4*i+3]=a.w;
                in.alv[4*i+0]=l.x; in.alv[4*i+1]=l.y; in.alv[4*i+2]=l.z; in.alv[4*i+3]=l.w;
            }
        } else {
            uint4 au = *(const uint4*)(am + erow + cb);
            uint4 lu = *(const uint4*)(al + erow + cb);
            const unsigned char* ab = (const unsigned char*)&au;
            const unsigned char* lb = (const unsigned char*)&lu;
            #pragma unroll
            for (int c = 0; c < 16; c++){ in.amv[c] = ab[c]; in.alv[c] = lb[c]; }
        }
        #pragma unroll
        for (int i = 0; i < 8; i++)
            in.ck4[i] = __ldg((const float4*)(ck + ((size_t)(b*KK2 + cb))*2) + i);
    };
    // ---- compute W values from raw inputs and store to smem buffer ----
    auto build_store = [&](const BuildIn& in, float* Wb){
        const unsigned* ew = (const unsigned*)in.eu;
        const float2* ckp = (const float2*)in.ck4;
        float wv[16];
        #pragma unroll
        for (int c = 0; c < 16; c++){
            __nv_bfloat162 e2 = *(__nv_bfloat162*)&ew[c>>1];
            float e = __bfloat162float((c & 1) ? e2.y : e2.x) * li;
            float dx = cqv.x - ckp[c].x;
            float dy = cqv.y - ckp[c].y;
            float r2 = fmaxf(dx*dx + dy*dy, 1e-30f);
            float d  = in.alv[c] ? 0.f : (r2 * frsqrt2(r2) * bsc);
            float w  = in.amv[c] ? 0.f : (e - d);
            wv[c] = __uint_as_float(to_tf32(w));
        }
        float* wd = Wb + brow*WPAD + bc0;
        *(float4*)(wd)      = make_float4(wv[0],  wv[1],  wv[2],  wv[3]);
        *(float4*)(wd + 4)  = make_float4(wv[4],  wv[5],  wv[6],  wv[7]);
        *(float4*)(wd + 8)  = make_float4(wv[8],  wv[9],  wv[10], wv[11]);
        *(float4*)(wd + 12) = make_float4(wv[12], wv[13], wv[14], wv[15]);
    };

    float C[4][8][4];
    #pragma unroll
    for (int a=0;a<4;a++)
        #pragma unroll
        for (int n=0;n<8;n++)
            #pragma unroll
            for (int c=0;c<4;c++) C[a][n][c]=0.f;

    {   // prologue: build tile 0
        BuildIn in0; load_in(0, in0);
        build_store(in0, smem);
    }
    __syncthreads();

    #pragma unroll 1
    for (int kt = 0; kt < 32; kt++){
        // ---- build(kt+1) into the other buffer: LDGs first, mma follows and hides them ----
        BuildIn in;
        if (kt < 31) load_in(kt + 1, in);

        // ---- mma(kt): A frags from Wb (4x LDS.32, conflict-free), B from g_Vp ----
        float* Wb = smem + (kt & 1) * (64*WPAD);
        const float* Bb = g_Vp + ((size_t)((b*8 + wc)*32 + kt))*4096;
        #pragma unroll
        for (int ks = 0; ks < 8; ks++){
            unsigned Af[4][4];
            #pragma unroll
            for (int mf = 0; mf < 4; mf++){
                #pragma unroll
                for (int r = 0; r < 4; r++){
                    int row = mf*16 + g + 8*(r & 1);
                    int col = ks*8 + t + 4*(r >> 1);
                    Af[mf][r] = __float_as_uint(Wb[row*WPAD + col]);
                }
            }
            uint2 Bf[8];
            #pragma unroll
            for (int nf = 0; nf < 8; nf++)
                Bf[nf] = *(const uint2*)(Bb + ((ks*8 + nf)*32 + lane)*2);
            #pragma unroll
            for (int mf = 0; mf < 4; mf++)
                #pragma unroll
                for (int nf = 0; nf < 8; nf++)
                    mma_tf32(C[mf][nf], Af[mf], (const unsigned*)&Bf[nf]);
        }

        if (kt < 31) build_store(in, smem + ((kt+1) & 1) * (64*WPAD));
        __syncthreads();   // orders build(kt+1) stores before mma(kt+1) reads,
                           // and mma(kt) reads before build(kt+2) rewrites this buffer
    }

    // ---- epilogue ----
    #pragma unroll
    for (int mf = 0; mf < 4; mf++)
        #pragma unroll
        for (int rh = 0; rh < 2; rh++){
            int row = qt*64 + mf*16 + g + 8*rh;
            float* orow = out + ((size_t)(b*QQ + row))*FVV;
            #pragma unroll
            for (int nf = 0; nf < 8; nf++){
                int fv = wc*64 + nf*8 + 2*t;
                *(float2*)(orow + fv) = make_float2(C[mf][nf][rh*2+0], C[mf][nf][rh*2+1]);
            }
        }
}

extern "C" void kernel_launch(void* const* d_in, const int* in_sizes, int n_in,
                              void* d_out, int out_size)
{
    const float*         q    = (const float*)d_in[0];
    const float*         k    = (const float*)d_in[1];
    const float*         v    = (const float*)d_in[2];
    const float*         cq   = (const float*)d_in[3];
    const float*         ck   = (const float*)d_in[4];
    const unsigned char* am   = (const unsigned char*)d_in[5];
    const unsigned char* al   = (const unsigned char*)d_in[6];
    const float*         bias = (const float*)d_in[7];
    float*               out  = (float*)d_out;

    static int smem_set = 0;
    if (!smem_set){
        cudaFuncSetAttribute(pass1_kernel, cudaFuncAttributeMaxDynamicSharedMemorySize, 68096);
        cudaFuncSetAttribute(pass2_kernel, cudaFuncAttributeMaxDynamicSharedMemorySize, 34816);
        smem_set = 1;
    }

    detect_mask_kernel<<<1, 1>>>(am);
    prep_qb_kernel<<<4096,  NTHREADS>>>(q);
    prep_kb_kernel<<<8192,  NTHREADS>>>(k);
    prep_v_kernel <<<16384, NTHREADS>>>(v);
    pass1_kernel<<<256, NTHREADS, 68096>>>();
    pass2_kernel<<<256, NTHREADS, 34816>>>(out, cq, ck, am, al, bias);
}

// round 8
// speedup vs baseline: 1.1132x; 1.1132x over previous
#include <cuda_runtime.h>
#include <cuda_bf16.h>
#include <math.h>

#define BB   8
#define QQ   2048
#define KK2  2048
#define FF   512
#define FVV  512
#define NTHREADS 256

// ---------------- scratch (device globals; no runtime allocation) ----------------
// bf16 A-blob (64x64): [ks4][mf4][lane32][4 b32]
// bf16 B-blob (64x64): [ks4][nf8][lane32][2 b32]
// tf32 B-blob (64x64): [ks8][nf8][lane32][2 b32]
__device__ __align__(16) unsigned g_Qpb[4194304];     // (b, qt32, ft8) bf16 A-blobs  16.8MB
__device__ __align__(16) unsigned g_Kpb[4194304];     // (b, kt32, ft8) bf16 B-blobs  16.8MB
__device__ __align__(16) float    g_Vp [8388608];     // (b, fvt8, kt32) tf32 B-blobs 33.5MB
__device__ __align__(16) __nv_bfloat16 g_E[33554432]; // exp(logits) row-major        67MB
__device__ float g_linv[BB*QQ];
__device__ int   g_mask_is_int32;

// ---------------- helpers ----------------
__device__ __forceinline__ unsigned to_tf32(float f){
    unsigned u; asm("cvt.rna.tf32.f32 %0, %1;" : "=r"(u) : "f"(f)); return u;
}
__device__ __forceinline__ void mma_tf32(float c[4], const unsigned* a, const unsigned* b){
    asm volatile("mma.sync.aligned.m16n8k8.row.col.f32.tf32.tf32.f32 "
        "{%0,%1,%2,%3}, {%4,%5,%6,%7}, {%8,%9}, {%0,%1,%2,%3};"
        : "+f"(c[0]), "+f"(c[1]), "+f"(c[2]), "+f"(c[3])
        : "r"(a[0]), "r"(a[1]), "r"(a[2]), "r"(a[3]), "r"(b[0]), "r"(b[1]));
}
__device__ __forceinline__ void mma_bf16(float c[4], const unsigned* a, const unsigned* b){
    asm volatile("mma.sync.aligned.m16n8k16.row.col.f32.bf16.bf16.f32 "
        "{%0,%1,%2,%3}, {%4,%5,%6,%7}, {%8,%9}, {%0,%1,%2,%3};"
        : "+f"(c[0]), "+f"(c[1]), "+f"(c[2]), "+f"(c[3])
        : "r"(a[0]), "r"(a[1]), "r"(a[2]), "r"(a[3]), "r"(b[0]), "r"(b[1]));
}
// exp on the FMA pipe: 2^(x*log2e), deg-5 poly (rel err ~2e-7 for |x| < 15)
__device__ __forceinline__ float fexp(float x){
    float t = x * 1.4426950408889634f;
    float r = rintf(t);
    float f = t - r;
    float p = 1.3333558146428443e-3f;
    p = fmaf(p, f, 9.618129107628477e-3f);
    p = fmaf(p, f, 5.550410866482158e-2f);
    p = fmaf(p, f, 2.402265069591007e-1f);
    p = fmaf(p, f, 6.931471805599453e-1f);
    p = fmaf(p, f, 1.0f);
    return __int_as_float(((int)r + 127) << 23) * p;
}
// rsqrt on FMA pipe, 2 Newton steps (~1e-6 rel)
__device__ __forceinline__ float frsqrt2(float x){
    float y = __int_as_float(0x5f3759df - (__float_as_int(x) >> 1));
    y = y * (1.5f - 0.5f * x * y * y);
    y = y * (1.5f - 0.5f * x * y * y);
    return y;
}
#define CP_ASYNC16(sm, gp) asm volatile("cp.async.cg.shared.global [%0], [%1], 16;" :: "r"(sm), "l"(gp))
#define CP_COMMIT()        asm volatile("cp.async.commit_group;" ::: "memory")
#define CP_WAIT0()         asm volatile("cp.async.wait_group 0;" ::: "memory")

// ---------------- mask dtype probe ----------------
__global__ void detect_mask_kernel(const unsigned char* am){
    unsigned nz = 0;
    #pragma unroll 8
    for (int i = 0; i < 1024; i++) nz |= am[4*i+1] | am[4*i+2] | am[4*i+3];
    g_mask_is_int32 = (nz == 0u) ? 1 : 0;
}

// ---------------- prep Q -> bf16 A-fragment blobs ----------------
__global__ void __launch_bounds__(NTHREADS) prep_qb_kernel(const float* __restrict__ q){
    int w = blockIdx.x * 8 + (threadIdx.x >> 5);
    int lane = threadIdx.x & 31, g = lane >> 2, t = lane & 3;
    int mf = w & 3, ks = (w>>2)&3, ft = (w>>4)&7, qt = (w>>7)&31, b = w>>12;
    unsigned rr[4];
    #pragma unroll
    for (int rh = 0; rh < 2; rh++){
        int row = qt*64 + mf*16 + g + 8*rh;
        const float* qp = q + ((size_t)(b*QQ + row))*FF + ft*64 + ks*16 + 2*t;
        float2 x0 = *(const float2*)qp;
        float2 x1 = *(const float2*)(qp + 8);
        __nv_bfloat162 h0 = __floats2bfloat162_rn(x0.x, x0.y);
        __nv_bfloat162 h1 = __floats2bfloat162_rn(x1.x, x1.y);
        rr[rh]   = *(unsigned*)&h0;
        rr[rh+2] = *(unsigned*)&h1;
    }
    size_t blob = ((size_t)((b*32 + qt)*8 + ft))*2048;
    *(uint4*)(g_Qpb + blob + ((ks*4 + mf)*32 + lane)*4) = make_uint4(rr[0],rr[1],rr[2],rr[3]);
}

// ---------------- prep K -> bf16 B-fragment blobs ----------------
__global__ void __launch_bounds__(NTHREADS) prep_kb_kernel(const float* __restrict__ k){
    int w = blockIdx.x * 8 + (threadIdx.x >> 5);
    int lane = threadIdx.x & 31, g = lane >> 2, t = lane & 3;
    int nf = w & 7, ks = (w>>3)&3, ft = (w>>5)&7, kt = (w>>8)&31, b = w>>13;
    int n = kt*64 + nf*8 + g;
    const float* kp = k + ((size_t)(b*KK2 + n))*FF + ft*64 + ks*16 + 2*t;
    float2 x0 = *(const float2*)kp;
    float2 x1 = *(const float2*)(kp + 8);
    __nv_bfloat162 h0 = __floats2bfloat162_rn(x0.x, x0.y);
    __nv_bfloat162 h1 = __floats2bfloat162_rn(x1.x, x1.y);
    size_t blob = ((size_t)((b*32 + kt)*8 + ft))*2048;
    *(uint2*)(g_Kpb + blob + ((ks*8 + nf)*32 + lane)*2) =
        make_uint2(*(unsigned*)&h0, *(unsigned*)&h1);
}

// ---------------- prep V -> tf32 B-fragment blobs ----------------
__global__ void __launch_bounds__(NTHREADS) prep_v_kernel(const float* __restrict__ v){
    int w = blockIdx.x * 8 + (threadIdx.x >> 5);
    int lane = threadIdx.x & 31, g = lane >> 2, t = lane & 3;
    int nf = w & 7, ks = (w>>3)&7, kt = (w>>6)&31, fvt = (w>>11)&7, b = w>>14;
    unsigned rr[2];
    #pragma unroll
    for (int j = 0; j < 2; j++){
        int kk = kt*64 + ks*8 + t + 4*j;
        int fv = fvt*64 + nf*8 + g;
        rr[j] = to_tf32(v[((size_t)(b*KK2 + kk))*FVV + fv]);
    }
    size_t blob = ((size_t)((b*8 + fvt)*32 + kt))*4096;
    *(uint2*)(g_Vp + blob + ((ks*8 + nf)*32 + lane)*2) = make_uint2(rr[0], rr[1]);
}

// ---------------- pass1: S = QK^T * scale (bf16 mma); E = exp(S); linv = 1/rowsum ----------------
__global__ void __launch_bounds__(NTHREADS, 1) pass1_kernel(void){
    extern __shared__ unsigned smem_u[];
    unsigned* smQ = smem_u;                    // 16384 words = 64KB
    float* l_s = (float*)(smem_u + 16384);

    int tid = threadIdx.x, lane = tid & 31, wc = tid >> 5;
    int g = lane >> 2, t = lane & 3;
    int b = blockIdx.x >> 5, qt = blockIdx.x & 31;
    const float SCALE = 0.044194173824159216f;  // 1/sqrt(512)

    {
        const uint4* src = (const uint4*)(g_Qpb + ((size_t)((b*32 + qt)*8))*2048);
        uint4* dst = (uint4*)smQ;
        #pragma unroll
        for (int i = 0; i < 16; i++) dst[tid + 256*i] = src[tid + 256*i];
    }
    __syncthreads();

    float rsl[4][2];
    #pragma unroll
    for (int a=0;a<4;a++){ rsl[a][0]=0.f; rsl[a][1]=0.f; }

    #pragma unroll 1
    for (int kb = 0; kb < 8; kb++){
        int kt = kb*4 + (wc >> 1);
        int nb = (wc & 1) * 4;

        float C[4][4][4];
        #pragma unroll
        for (int a=0;a<4;a++)
            #pragma unroll
            for (int bb=0;bb<4;bb++)
                #pragma unroll
                for (int c=0;c<4;c++) C[a][bb][c]=0.f;

        #pragma unroll 1
        for (int ft = 0; ft < 8; ft++){
            const unsigned* As = smQ + ft*2048;
            const unsigned* Bb = g_Kpb + ((size_t)((b*32 + kt)*8 + ft))*2048;
            #pragma unroll
            for (int ks = 0; ks < 4; ks++){
                uint4 Af[4];
                #pragma unroll
                for (int mf=0; mf<4; mf++)
                    Af[mf] = *(const uint4*)(As + ((ks*4 + mf)*32 + lane)*4);
                uint2 Bf[4];
                #pragma unroll
                for (int nf=0; nf<4; nf++)
                    Bf[nf] = *(const uint2*)(Bb + ((ks*8 + nb + nf)*32 + lane)*2);
                #pragma unroll
                for (int mf=0; mf<4; mf++)
                    #pragma unroll
                    for (int nf=0; nf<4; nf++)
                        mma_bf16(C[mf][nf], (const unsigned*)&Af[mf], (const unsigned*)&Bf[nf]);
            }
        }

        #pragma unroll
        for (int mf = 0; mf < 4; mf++)
            #pragma unroll
            for (int rh = 0; rh < 2; rh++){
                int row = qt*64 + mf*16 + g + 8*rh;
                float rs = 0.f;
                #pragma unroll
                for (int nf = 0; nf < 4; nf++){
                    float e0 = fexp(C[mf][nf][rh*2+0] * SCALE);
                    float e1 = fexp(C[mf][nf][rh*2+1] * SCALE);
                    rs += e0 + e1;
                    int kcol = kb*256 + wc*32 + nf*8 + 2*t;
                    size_t idx = ((size_t)(b*QQ + row))*KK2 + kcol;
                    ((__nv_bfloat162*)g_E)[idx >> 1] = __floats2bfloat162_rn(e0, e1);
                }
                rsl[mf][rh] += rs;
            }
    }

    #pragma unroll
    for (int mf = 0; mf < 4; mf++)
        #pragma unroll
        for (int rh = 0; rh < 2; rh++){
            float rs = rsl[mf][rh];
            rs += __shfl_xor_sync(0xffffffffu, rs, 1);
            rs += __shfl_xor_sync(0xffffffffu, rs, 2);
            if (t == 0) l_s[wc*64 + mf*16 + g + 8*rh] = rs;
        }
    __syncthreads();
    if (tid < 64){
        float s = 0.f;
        #pragma unroll
        for (int w = 0; w < 8; w++) s += l_s[w*64 + tid];
        g_linv[b*QQ + qt*64 + tid] = 1.0f / s;
    }
}

// ---------------- pass2 (fused, cp.async-pipelined): W built in smem; O = W*V ----------------
// smem map (bytes):
//   [0, 34816)        W double buffer: 2 x 64 x 68 floats
//   [34816, 53248)    E stage:  2 x 64 rows x 144B (row = 64 bf16 + pad)
//   [53248, 88064)    am stage: 2 x 64 rows x 272B (int32 mode; 80B rows in u8 mode)
//   [88064, 122880)   al stage: same
//   [122880, 123904)  ck stage: 2 x 512B
#define WPAD 68
#define OFF_E  34816
#define OFF_AM 53248
#define OFF_AL 88064
#define OFF_CK 122880
#define SMEM_P2 123904

__global__ void __launch_bounds__(NTHREADS, 1) pass2_kernel(
    float* __restrict__ out,
    const float* __restrict__ cq, const float* __restrict__ ck,
    const unsigned char* __restrict__ am, const unsigned char* __restrict__ al,
    const float* __restrict__ bias)
{
    extern __shared__ char sm[];
    float* Wbuf = (float*)sm;
    const unsigned smaddr = (unsigned)__cvta_generic_to_shared(sm);

    int tid = threadIdx.x, lane = tid & 31, wc = tid >> 5;
    int g = lane >> 2, t = lane & 3;
    int b = blockIdx.x >> 5, qt = blockIdx.x & 31;

    // build role: thread owns row brow, 16 cols at bc0 (within k-tile)
    const int brow = wc*8 + (lane >> 2);
    const int bc0  = (lane & 3) * 16;
    const float2 cqv = *(const float2*)(cq + ((size_t)(b*QQ + qt*64 + brow))*2);
    const float li   = g_linv[b*QQ + qt*64 + brow];
    const float bsc = __ldg(bias);
    const int m32 = g_mask_is_int32;

    // loader role: thread stages row lr, 16B chunk lc (of E/masks)
    const int lr = tid >> 2, lc = tid & 3;
    const size_t lrow = ((size_t)(b*QQ + qt*64 + lr))*KK2;   // element row base

    // ---- issue cp.async for tile kt into stage p ----
    auto issue_cp = [&](int kt, int p){
        // E: 64 rows x 128B, row stride 144
        {
            const __nv_bfloat16* src = g_E + lrow + kt*64;
            unsigned dst = smaddr + OFF_E + p*9216 + lr*144;
            CP_ASYNC16(dst + lc*16,      src + lc*8);
            CP_ASYNC16(dst + (lc+4)*16,  src + (lc+4)*8);
        }
        if (m32){
            const int* asrc = (const int*)am + lrow + kt*64;
            const int* lsrc = (const int*)al + lrow + kt*64;
            unsigned adst = smaddr + OFF_AM + p*17408 + lr*272;
            unsigned ldst = smaddr + OFF_AL + p*17408 + lr*272;
            #pragma unroll
            for (int i = 0; i < 4; i++){
                CP_ASYNC16(adst + (lc+4*i)*16, asrc + (lc+4*i)*4);
                CP_ASYNC16(ldst + (lc+4*i)*16, lsrc + (lc+4*i)*4);
            }
        } else {
            const unsigned char* asrc = am + lrow + kt*64;
            const unsigned char* lsrc = al + lrow + kt*64;
            if (lc == 0){ /* one 16B chunk per row quarter handled below */ }
            // 64 rows x 64B = 4 chunks/row; thread (lr, lc) does chunk lc
            CP_ASYNC16(smaddr + OFF_AM + p*17408 + lr*80 + lc*16, asrc + lc*16);
            CP_ASYNC16(smaddr + OFF_AL + p*17408 + lr*80 + lc*16, lsrc + lc*16);
        }
        if (tid < 32)
            CP_ASYNC16(smaddr + OFF_CK + p*512 + tid*16,
                       ck + ((size_t)(b*KK2 + kt*64))*2 + tid*4);
        CP_COMMIT();
    };

    // ---- build W tile from stage p into W buffer ----
    auto build_tile = [&](int p, float* Wb){
        const char* eb = sm + OFF_E + p*9216 + brow*144 + bc0*2;
        uint4 e0 = *(const uint4*)eb;
        uint4 e1 = *(const uint4*)(eb + 16);
        unsigned ew[8] = {e0.x,e0.y,e0.z,e0.w,e1.x,e1.y,e1.z,e1.w};
        int amv[16], alv[16];
        if (m32){
            const uint4* ap = (const uint4*)(sm + OFF_AM + p*17408 + brow*272 + bc0*4);
            const uint4* lp = (const uint4*)(sm + OFF_AL + p*17408 + brow*272 + bc0*4);
            #pragma unroll
            for (int i = 0; i < 4; i++){
                uint4 a = ap[i], l = lp[i];
                amv[4*i+0]=a.x; amv[4*i+1]=a.y; amv[4*i+2]=a.z; amv[4*i+3]=a.w;
                alv[4*i+0]=l.x; alv[4*i+1]=l.y; alv[4*i+2]=l.z; alv[4*i+3]=l.w;
            }
        } else {
            uint4 au = *(const uint4*)(sm + OFF_AM + p*17408 + brow*80 + bc0);
            uint4 lu = *(const uint4*)(sm + OFF_AL + p*17408 + brow*80 + bc0);
            const unsigned char* ab = (const unsigned char*)&au;
            const unsigned char* lb = (const unsigned char*)&lu;
            #pragma unroll
            for (int c = 0; c < 16; c++){ amv[c] = ab[c]; alv[c] = lb[c]; }
        }
        const float2* ckp = (const float2*)(sm + OFF_CK + p*512 + bc0*8);
        float wv[16];
        #pragma unroll
        for (int c = 0; c < 16; c++){
            __nv_bfloat162 e2 = *(__nv_bfloat162*)&ew[c>>1];
            float e = __bfloat162float((c & 1) ? e2.y : e2.x) * li;
            float2 ckv = ckp[c];
            float dx = cqv.x - ckv.x;
            float dy = cqv.y - ckv.y;
            float r2 = fmaxf(dx*dx + dy*dy, 1e-30f);
            float d  = alv[c] ? 0.f : (r2 * frsqrt2(r2) * bsc);
            float w  = amv[c] ? 0.f : (e - d);
            wv[c] = __uint_as_float(to_tf32(w));
        }
        float* wd = Wb + brow*WPAD + bc0;
        *(float4*)(wd)      = make_float4(wv[0],  wv[1],  wv[2],  wv[3]);
        *(float4*)(wd + 4)  = make_float4(wv[4],  wv[5],  wv[6],  wv[7]);
        *(float4*)(wd + 8)  = make_float4(wv[8],  wv[9],  wv[10], wv[11]);
        *(float4*)(wd + 12) = make_float4(wv[12], wv[13], wv[14], wv[15]);
    };

    float C[4][8][4];
    #pragma unroll
    for (int a=0;a<4;a++)
        #pragma unroll
        for (int n=0;n<8;n++)
            #pragma unroll
            for (int c=0;c<4;c++) C[a][n][c]=0.f;

    // prologue: stage + build tile 0
    issue_cp(0, 0);
    CP_WAIT0();
    __syncthreads();
    build_tile(0, Wbuf);
    __syncthreads();

    #pragma unroll 1
    for (int kt = 0; kt < 32; kt++){
        if (kt < 31) issue_cp(kt + 1, (kt + 1) & 1);   // async; lands during mma

        // ---- mma(kt): A frags from W[kt&1] (4x LDS.32, conflict-free), B from g_Vp ----
        float* Wb = Wbuf + (kt & 1) * (64*WPAD);
        const float* Bb = g_Vp + ((size_t)((b*8 + wc)*32 + kt))*4096;
        #pragma unroll
        for (int ks = 0; ks < 8; ks++){
            unsigned Af[4][4];
            #pragma unroll
            for (int mf = 0; mf < 4; mf++){
                #pragma unroll
                for (int r = 0; r < 4; r++){
                    int row = mf*16 + g + 8*(r & 1);
                    int col = ks*8 + t + 4*(r >> 1);
                    Af[mf][r] = __float_as_uint(Wb[row*WPAD + col]);
                }
            }
            uint2 Bf[8];
            #pragma unroll
            for (int nf = 0; nf < 8; nf++)
                Bf[nf] = *(const uint2*)(Bb + ((ks*8 + nf)*32 + lane)*2);
            #pragma unroll
            for (int mf = 0; mf < 4; mf++)
                #pragma unroll
                for (int nf = 0; nf < 8; nf++)
                    mma_tf32(C[mf][nf], Af[mf], (const unsigned*)&Bf[nf]);
        }

        if (kt < 31){
            CP_WAIT0();
            __syncthreads();                    // staged data visible to all
            build_tile((kt + 1) & 1, Wbuf + ((kt + 1) & 1) * (64*WPAD));
        }
        __syncthreads();                        // build stores before mma(kt+1) reads;
                                                // stage reads before cp(kt+2) rewrites
    }

    // ---- epilogue ----
    #pragma unroll
    for (int mf = 0; mf < 4; mf++)
        #pragma unroll
        for (int rh = 0; rh < 2; rh++){
            int row = qt*64 + mf*16 + g + 8*rh;
            float* orow = out + ((size_t)(b*QQ + row))*FVV;
            #pragma unroll
            for (int nf = 0; nf < 8; nf++){
                int fv = wc*64 + nf*8 + 2*t;
                *(float2*)(orow + fv) = make_float2(C[mf][nf][rh*2+0], C[mf][nf][rh*2+1]);
            }
        }
}

extern "C" void kernel_launch(void* const* d_in, const int* in_sizes, int n_in,
                              void* d_out, int out_size)
{
    const float*         q    = (const float*)d_in[0];
    const float*         k    = (const float*)d_in[1];
    const float*         v    = (const float*)d_in[2];
    const float*         cq   = (const float*)d_in[3];
    const float*         ck   = (const float*)d_in[4];
    const unsigned char* am   = (const unsigned char*)d_in[5];
    const unsigned char* al   = (const unsigned char*)d_in[6];
    const float*         bias = (const float*)d_in[7];
    float*               out  = (float*)d_out;

    static int smem_set = 0;
    if (!smem_set){
        cudaFuncSetAttribute(pass1_kernel, cudaFuncAttributeMaxDynamicSharedMemorySize, 68096);
        cudaFuncSetAttribute(pass2_kernel, cudaFuncAttributeMaxDynamicSharedMemorySize, SMEM_P2);
        smem_set = 1;
    }

    detect_mask_kernel<<<1, 1>>>(am);
    prep_qb_kernel<<<4096,  NTHREADS>>>(q);
    prep_kb_kernel<<<8192,  NTHREADS>>>(k);
    prep_v_kernel <<<16384, NTHREADS>>>(v);
    pass1_kernel<<<256, NTHREADS, 68096>>>();
    pass2_kernel<<<256, NTHREADS, SMEM_P2>>>(out, cq, ck, am, al, bias);
}

// round 9
// speedup vs baseline: 1.2695x; 1.1404x over previous
#include <cuda_runtime.h>
#include <cuda_bf16.h>
#include <math.h>

#define BB   8
#define QQ   2048
#define KK2  2048
#define FF   512
#define FVV  512
#define NTHREADS 256

// ---------------- scratch (device globals; no runtime allocation) ----------------
// bf16 A-blob (64x64): [ks4][mf4][lane32][4 b32]
// bf16 B-blob (64x64): [ks4][nf8][lane32][2 b32]
// tf32 B-blob (64x64): [ks8][nf8][lane32][2 b32]
__device__ __align__(16) unsigned g_Qpb[4194304];     // (b, qt32, ft8) bf16 A-blobs  16.8MB
__device__ __align__(16) unsigned g_Kpb[4194304];     // (b, kt32, ft8) bf16 B-blobs  16.8MB
__device__ __align__(16) float    g_Vp [8388608];     // (b, fvt8, kt32) tf32 B-blobs 33.5MB
__device__ __align__(16) __nv_bfloat16 g_E[33554432]; // exp(logits) row-major        67MB
__device__ float g_linv[BB*QQ];
__device__ int   g_mask_is_int32;

// ---------------- helpers ----------------
__device__ __forceinline__ unsigned to_tf32(float f){
    unsigned u; asm("cvt.rna.tf32.f32 %0, %1;" : "=r"(u) : "f"(f)); return u;
}
__device__ __forceinline__ void mma_tf32(float c[4], const unsigned* a, const unsigned* b){
    asm volatile("mma.sync.aligned.m16n8k8.row.col.f32.tf32.tf32.f32 "
        "{%0,%1,%2,%3}, {%4,%5,%6,%7}, {%8,%9}, {%0,%1,%2,%3};"
        : "+f"(c[0]), "+f"(c[1]), "+f"(c[2]), "+f"(c[3])
        : "r"(a[0]), "r"(a[1]), "r"(a[2]), "r"(a[3]), "r"(b[0]), "r"(b[1]));
}
__device__ __forceinline__ void mma_bf16(float c[4], const unsigned* a, const unsigned* b){
    asm volatile("mma.sync.aligned.m16n8k16.row.col.f32.bf16.bf16.f32 "
        "{%0,%1,%2,%3}, {%4,%5,%6,%7}, {%8,%9}, {%0,%1,%2,%3};"
        : "+f"(c[0]), "+f"(c[1]), "+f"(c[2]), "+f"(c[3])
        : "r"(a[0]), "r"(a[1]), "r"(a[2]), "r"(a[3]), "r"(b[0]), "r"(b[1]));
}
// exp on the FMA pipe: 2^(x*log2e), deg-5 poly (rel err ~2e-7 for |x| < 15)
__device__ __forceinline__ float fexp(float x){
    float t = x * 1.4426950408889634f;
    float r = rintf(t);
    float f = t - r;
    float p = 1.3333558146428443e-3f;
    p = fmaf(p, f, 9.618129107628477e-3f);
    p = fmaf(p, f, 5.550410866482158e-2f);
    p = fmaf(p, f, 2.402265069591007e-1f);
    p = fmaf(p, f, 6.931471805599453e-1f);
    p = fmaf(p, f, 1.0f);
    return __int_as_float(((int)r + 127) << 23) * p;
}
// rsqrt on FMA pipe, 2 Newton steps (~1e-6 rel)
__device__ __forceinline__ float frsqrt2(float x){
    float y = __int_as_float(0x5f3759df - (__float_as_int(x) >> 1));
    y = y * (1.5f - 0.5f * x * y * y);
    y = y * (1.5f - 0.5f * x * y * y);
    return y;
}

// ---------------- mask dtype probe ----------------
__global__ void detect_mask_kernel(const unsigned char* am){
    unsigned nz = 0;
    #pragma unroll 8
    for (int i = 0; i < 1024; i++) nz |= am[4*i+1] | am[4*i+2] | am[4*i+3];
    g_mask_is_int32 = (nz == 0u) ? 1 : 0;
}

// ---------------- prep Q -> bf16 A-fragment blobs ----------------
__global__ void __launch_bounds__(NTHREADS) prep_qb_kernel(const float* __restrict__ q){
    int w = blockIdx.x * 8 + (threadIdx.x >> 5);
    int lane = threadIdx.x & 31, g = lane >> 2, t = lane & 3;
    int mf = w & 3, ks = (w>>2)&3, ft = (w>>4)&7, qt = (w>>7)&31, b = w>>12;
    unsigned rr[4];
    #pragma unroll
    for (int rh = 0; rh < 2; rh++){
        int row = qt*64 + mf*16 + g + 8*rh;
        const float* qp = q + ((size_t)(b*QQ + row))*FF + ft*64 + ks*16 + 2*t;
        float2 x0 = *(const float2*)qp;
        float2 x1 = *(const float2*)(qp + 8);
        __nv_bfloat162 h0 = __floats2bfloat162_rn(x0.x, x0.y);
        __nv_bfloat162 h1 = __floats2bfloat162_rn(x1.x, x1.y);
        rr[rh]   = *(unsigned*)&h0;
        rr[rh+2] = *(unsigned*)&h1;
    }
    size_t blob = ((size_t)((b*32 + qt)*8 + ft))*2048;
    *(uint4*)(g_Qpb + blob + ((ks*4 + mf)*32 + lane)*4) = make_uint4(rr[0],rr[1],rr[2],rr[3]);
}

// ---------------- prep K -> bf16 B-fragment blobs ----------------
__global__ void __launch_bounds__(NTHREADS) prep_kb_kernel(const float* __restrict__ k){
    int w = blockIdx.x * 8 + (threadIdx.x >> 5);
    int lane = threadIdx.x & 31, g = lane >> 2, t = lane & 3;
    int nf = w & 7, ks = (w>>3)&3, ft = (w>>5)&7, kt = (w>>8)&31, b = w>>13;
    int n = kt*64 + nf*8 + g;
    const float* kp = k + ((size_t)(b*KK2 + n))*FF + ft*64 + ks*16 + 2*t;
    float2 x0 = *(const float2*)kp;
    float2 x1 = *(const float2*)(kp + 8);
    __nv_bfloat162 h0 = __floats2bfloat162_rn(x0.x, x0.y);
    __nv_bfloat162 h1 = __floats2bfloat162_rn(x1.x, x1.y);
    size_t blob = ((size_t)((b*32 + kt)*8 + ft))*2048;
    *(uint2*)(g_Kpb + blob + ((ks*8 + nf)*32 + lane)*2) =
        make_uint2(*(unsigned*)&h0, *(unsigned*)&h1);
}

// ---------------- prep V -> tf32 B-fragment blobs ----------------
__global__ void __launch_bounds__(NTHREADS) prep_v_kernel(const float* __restrict__ v){
    int w = blockIdx.x * 8 + (threadIdx.x >> 5);
    int lane = threadIdx.x & 31, g = lane >> 2, t = lane & 3;
    int nf = w & 7, ks = (w>>3)&7, kt = (w>>6)&31, fvt = (w>>11)&7, b = w>>14;
    unsigned rr[2];
    #pragma unroll
    for (int j = 0; j < 2; j++){
        int kk = kt*64 + ks*8 + t + 4*j;
        int fv = fvt*64 + nf*8 + g;
        rr[j] = to_tf32(v[((size_t)(b*KK2 + kk))*FVV + fv]);
    }
    size_t blob = ((size_t)((b*8 + fvt)*32 + kt))*4096;
    *(uint2*)(g_Vp + blob + ((ks*8 + nf)*32 + lane)*2) = make_uint2(rr[0], rr[1]);
}

// ---------------- pass1: S = QK^T * scale (bf16 mma); E = exp(S); linv = 1/rowsum ----------------
__global__ void __launch_bounds__(NTHREADS, 1) pass1_kernel(void){
    extern __shared__ unsigned smem_u[];
    unsigned* smQ = smem_u;                    // 16384 words = 64KB
    float* l_s = (float*)(smem_u + 16384);

    int tid = threadIdx.x, lane = tid & 31, wc = tid >> 5;
    int g = lane >> 2, t = lane & 3;
    int b = blockIdx.x >> 5, qt = blockIdx.x & 31;
    const float SCALE = 0.044194173824159216f;  // 1/sqrt(512)

    {
        const uint4* src = (const uint4*)(g_Qpb + ((size_t)((b*32 + qt)*8))*2048);
        uint4* dst = (uint4*)smQ;
        #pragma unroll
        for (int i = 0; i < 16; i++) dst[tid + 256*i] = src[tid + 256*i];
    }
    __syncthreads();

    float rsl[4][2];
    #pragma unroll
    for (int a=0;a<4;a++){ rsl[a][0]=0.f; rsl[a][1]=0.f; }

    #pragma unroll 1
    for (int kb = 0; kb < 8; kb++){
        int kt = kb*4 + (wc >> 1);
        int nb = (wc & 1) * 4;

        float C[4][4][4];
        #pragma unroll
        for (int a=0;a<4;a++)
            #pragma unroll
            for (int bb=0;bb<4;bb++)
                #pragma unroll
                for (int c=0;c<4;c++) C[a][bb][c]=0.f;

        #pragma unroll 1
        for (int ft = 0; ft < 8; ft++){
            const unsigned* As = smQ + ft*2048;
            const unsigned* Bb = g_Kpb + ((size_t)((b*32 + kt)*8 + ft))*2048;
            #pragma unroll
            for (int ks = 0; ks < 4; ks++){
                uint4 Af[4];
                #pragma unroll
                for (int mf=0; mf<4; mf++)
                    Af[mf] = *(const uint4*)(As + ((ks*4 + mf)*32 + lane)*4);
                uint2 Bf[4];
                #pragma unroll
                for (int nf=0; nf<4; nf++)
                    Bf[nf] = *(const uint2*)(Bb + ((ks*8 + nb + nf)*32 + lane)*2);
                #pragma unroll
                for (int mf=0; mf<4; mf++)
                    #pragma unroll
                    for (int nf=0; nf<4; nf++)
                        mma_bf16(C[mf][nf], (const unsigned*)&Af[mf], (const unsigned*)&Bf[nf]);
            }
        }

        #pragma unroll
        for (int mf = 0; mf < 4; mf++)
            #pragma unroll
            for (int rh = 0; rh < 2; rh++){
                int row = qt*64 + mf*16 + g + 8*rh;
                float rs = 0.f;
                #pragma unroll
                for (int nf = 0; nf < 4; nf++){
                    float e0 = fexp(C[mf][nf][rh*2+0] * SCALE);
                    float e1 = fexp(C[mf][nf][rh*2+1] * SCALE);
                    rs += e0 + e1;
                    int kcol = kb*256 + wc*32 + nf*8 + 2*t;
                    size_t idx = ((size_t)(b*QQ + row))*KK2 + kcol;
                    ((__nv_bfloat162*)g_E)[idx >> 1] = __floats2bfloat162_rn(e0, e1);
                }
                rsl[mf][rh] += rs;
            }
    }

    #pragma unroll
    for (int mf = 0; mf < 4; mf++)
        #pragma unroll
        for (int rh = 0; rh < 2; rh++){
            float rs = rsl[mf][rh];
            rs += __shfl_xor_sync(0xffffffffu, rs, 1);
            rs += __shfl_xor_sync(0xffffffffu, rs, 2);
            if (t == 0) l_s[wc*64 + mf*16 + g + 8*rh] = rs;
        }
    __syncthreads();
    if (tid < 64){
        float s = 0.f;
        #pragma unroll
        for (int w = 0; w < 8; w++) s += l_s[w*64 + tid];
        g_linv[b*QQ + qt*64 + tid] = 1.0f / s;
    }
}

// ---------------- pass2 (fused, 32-row q-tiles, 2 CTAs/SM): W in smem; O = W*V ----------------
// CTA = (b, qtile of 32 rows) x all 512 fv. Cross-CTA overlap hides build latency.
// W smem: double-buffered 32 x 68 floats. A-frag gather 4x LDS.32, bank-conflict-free.
#define WPAD 68
__global__ void __launch_bounds__(NTHREADS, 2) pass2_kernel(
    float* __restrict__ out,
    const float* __restrict__ cq, const float* __restrict__ ck,
    const unsigned char* __restrict__ am, const unsigned char* __restrict__ al,
    const float* __restrict__ bias)
{
    extern __shared__ float smem[];   // 2 * 32*68 floats = 17408 B
    int tid = threadIdx.x, lane = tid & 31, wc = tid >> 5;
    int g = lane >> 2, t = lane & 3;
    int b = blockIdx.x >> 6, qt = blockIdx.x & 63;
    const int q0 = qt*32;

    // build role: thread owns row brow (0..31), 8 cols at bc0 (within 64-col k-tile)
    const int brow = tid >> 3;
    const int bc0  = (tid & 7) * 8;
    const float2 cqv = *(const float2*)(cq + ((size_t)(b*QQ + q0 + brow))*2);
    const float li   = g_linv[b*QQ + q0 + brow];
    const size_t erow = ((size_t)(b*QQ + q0 + brow))*KK2;
    const float bsc = __ldg(bias);
    const int m32 = g_mask_is_int32;

    float C[2][8][4];
    #pragma unroll
    for (int a=0;a<2;a++)
        #pragma unroll
        for (int n=0;n<8;n++)
            #pragma unroll
            for (int c=0;c<4;c++) C[a][n][c]=0.f;

    #pragma unroll 1
    for (int kt = 0; kt < 32; kt++){
        float* Wb = smem + (kt & 1) * (32*WPAD);

        // ---- build W tile (32x64): 8 elems per thread ----
        {
            int cb = kt*64 + bc0;
            uint4 eu = *(const uint4*)(g_E + erow + cb);       // 8 bf16
            const unsigned* ew = (const unsigned*)&eu;
            int amv[8], alv[8];
            if (m32){
                const int4* ap = (const int4*)((const int*)am + erow + cb);
                const int4* lp = (const int4*)((const int*)al + erow + cb);
                int4 a0 = ap[0], a1 = ap[1], l0 = lp[0], l1 = lp[1];
                amv[0]=a0.x; amv[1]=a0.y; amv[2]=a0.z; amv[3]=a0.w;
                amv[4]=a1.x; amv[5]=a1.y; amv[6]=a1.z; amv[7]=a1.w;
                alv[0]=l0.x; alv[1]=l0.y; alv[2]=l0.z; alv[3]=l0.w;
                alv[4]=l1.x; alv[5]=l1.y; alv[6]=l1.z; alv[7]=l1.w;
            } else {
                uint2 au = *(const uint2*)(am + erow + cb);
                uint2 lu = *(const uint2*)(al + erow + cb);
                const unsigned char* ab = (const unsigned char*)&au;
                const unsigned char* lb = (const unsigned char*)&lu;
                #pragma unroll
                for (int c = 0; c < 8; c++){ amv[c] = ab[c]; alv[c] = lb[c]; }
            }
            float4 ck4[4];
            #pragma unroll
            for (int i = 0; i < 4; i++)
                ck4[i] = __ldg((const float4*)(ck + ((size_t)(b*KK2 + cb))*2) + i);
            const float2* ckp = (const float2*)&ck4[0];

            float wv[8];
            #pragma unroll
            for (int c = 0; c < 8; c++){
                __nv_bfloat162 e2 = *(__nv_bfloat162*)&ew[c>>1];
                float e = __bfloat162float((c & 1) ? e2.y : e2.x) * li;
                float dx = cqv.x - ckp[c].x;
                float dy = cqv.y - ckp[c].y;
                float r2 = fmaxf(dx*dx + dy*dy, 1e-30f);
                float d  = alv[c] ? 0.f : (r2 * frsqrt2(r2) * bsc);
                float w  = amv[c] ? 0.f : (e - d);
                wv[c] = __uint_as_float(to_tf32(w));
            }
            float* wd = Wb + brow*WPAD + bc0;
            *(float4*)(wd)     = make_float4(wv[0], wv[1], wv[2], wv[3]);
            *(float4*)(wd + 4) = make_float4(wv[4], wv[5], wv[6], wv[7]);
        }
        __syncthreads();

        // ---- mma: A frags from Wb (4x LDS.32, conflict-free), B from g_Vp ----
        const float* Bb = g_Vp + ((size_t)((b*8 + wc)*32 + kt))*4096;
        #pragma unroll
        for (int ks = 0; ks < 8; ks++){
            unsigned Af[2][4];
            #pragma unroll
            for (int mf = 0; mf < 2; mf++){
                #pragma unroll
                for (int r = 0; r < 4; r++){
                    int row = mf*16 + g + 8*(r & 1);
                    int col = ks*8 + t + 4*(r >> 1);
                    Af[mf][r] = __float_as_uint(Wb[row*WPAD + col]);
                }
            }
            uint2 Bf[8];
            #pragma unroll
            for (int nf = 0; nf < 8; nf++)
                Bf[nf] = *(const uint2*)(Bb + ((ks*8 + nf)*32 + lane)*2);
            #pragma unroll
            for (int mf = 0; mf < 2; mf++)
                #pragma unroll
                for (int nf = 0; nf < 8; nf++)
                    mma_tf32(C[mf][nf], Af[mf], (const unsigned*)&Bf[nf]);
        }
        // next build writes the other buffer; sync(kt+1) transitively orders
        // mma(kt) readers before build(kt+2) rewrites this buffer.
    }

    // ---- epilogue ----
    #pragma unroll
    for (int mf = 0; mf < 2; mf++)
        #pragma unroll
        for (int rh = 0; rh < 2; rh++){
            int row = q0 + mf*16 + g + 8*rh;
            float* orow = out + ((size_t)(b*QQ + row))*FVV;
            #pragma unroll
            for (int nf = 0; nf < 8; nf++){
                int fv = wc*64 + nf*8 + 2*t;
                *(float2*)(orow + fv) = make_float2(C[mf][nf][rh*2+0], C[mf][nf][rh*2+1]);
            }
        }
}

extern "C" void kernel_launch(void* const* d_in, const int* in_sizes, int n_in,
                              void* d_out, int out_size)
{
    const float*         q    = (const float*)d_in[0];
    const float*         k    = (const float*)d_in[1];
    const float*         v    = (const float*)d_in[2];
    const float*         cq   = (const float*)d_in[3];
    const float*         ck   = (const float*)d_in[4];
    const unsigned char* am   = (const unsigned char*)d_in[5];
    const unsigned char* al   = (const unsigned char*)d_in[6];
    const float*         bias = (const float*)d_in[7];
    float*               out  = (float*)d_out;

    static int smem_set = 0;
    if (!smem_set){
        cudaFuncSetAttribute(pass1_kernel, cudaFuncAttributeMaxDynamicSharedMemorySize, 68096);
        cudaFuncSetAttribute(pass2_kernel, cudaFuncAttributeMaxDynamicSharedMemorySize, 17408);
        smem_set = 1;
    }

    detect_mask_kernel<<<1, 1>>>(am);
    prep_qb_kernel<<<4096,  NTHREADS>>>(q);
    prep_kb_kernel<<<8192,  NTHREADS>>>(k);
    prep_v_kernel <<<16384, NTHREADS>>>(v);
    pass1_kernel<<<256, NTHREADS, 68096>>>();
    pass2_kernel<<<512, NTHREADS, 17408>>>(out, cq, ck, am, al, bias);
}

// round 10
// speedup vs baseline: 1.3387x; 1.0545x over previous
#include <cuda_runtime.h>
#include <cuda_bf16.h>
#include <math.h>

#define BB   8
#define QQ   2048
#define KK2  2048
#define FF   512
#define FVV  512
#define NTHREADS 256

// ---------------- scratch (device globals; no runtime allocation) ----------------
// bf16 A-blob (64x64): [ks4][mf4][lane32][4 b32]
// bf16 B-blob (64x64): [ks4][nf8][lane32][2 b32]
// tf32 B-blob (64x64): [ks8][nf8][lane32][2 b32]
__device__ __align__(16) unsigned g_Qpb[4194304];     // (b, qt32, ft8) bf16 A-blobs  16.8MB
__device__ __align__(16) unsigned g_Kpb[4194304];     // (b, kt32, ft8) bf16 B-blobs  16.8MB
__device__ __align__(16) float    g_Vp [8388608];     // (b, fvt8, kt32) tf32 B-blobs 33.5MB
__device__ __align__(16) __nv_bfloat16 g_E[33554432]; // exp(logits) row-major        67MB
__device__ float g_linv[BB*QQ];
__device__ int   g_mask_is_int32;

// ---------------- helpers ----------------
__device__ __forceinline__ unsigned to_tf32(float f){
    unsigned u; asm("cvt.rna.tf32.f32 %0, %1;" : "=r"(u) : "f"(f)); return u;
}
__device__ __forceinline__ void mma_tf32(float c[4], const unsigned* a, const unsigned* b){
    asm volatile("mma.sync.aligned.m16n8k8.row.col.f32.tf32.tf32.f32 "
        "{%0,%1,%2,%3}, {%4,%5,%6,%7}, {%8,%9}, {%0,%1,%2,%3};"
        : "+f"(c[0]), "+f"(c[1]), "+f"(c[2]), "+f"(c[3])
        : "r"(a[0]), "r"(a[1]), "r"(a[2]), "r"(a[3]), "r"(b[0]), "r"(b[1]));
}
__device__ __forceinline__ void mma_bf16(float c[4], const unsigned* a, const unsigned* b){
    asm volatile("mma.sync.aligned.m16n8k16.row.col.f32.bf16.bf16.f32 "
        "{%0,%1,%2,%3}, {%4,%5,%6,%7}, {%8,%9}, {%0,%1,%2,%3};"
        : "+f"(c[0]), "+f"(c[1]), "+f"(c[2]), "+f"(c[3])
        : "r"(a[0]), "r"(a[1]), "r"(a[2]), "r"(a[3]), "r"(b[0]), "r"(b[1]));
}
// exp on the FMA pipe: 2^(x*log2e), deg-5 poly (rel err ~2e-7 for |x| < 15)
__device__ __forceinline__ float fexp(float x){
    float t = x * 1.4426950408889634f;
    float r = rintf(t);
    float f = t - r;
    float p = 1.3333558146428443e-3f;
    p = fmaf(p, f, 9.618129107628477e-3f);
    p = fmaf(p, f, 5.550410866482158e-2f);
    p = fmaf(p, f, 2.402265069591007e-1f);
    p = fmaf(p, f, 6.931471805599453e-1f);
    p = fmaf(p, f, 1.0f);
    return __int_as_float(((int)r + 127) << 23) * p;
}
// rsqrt on FMA pipe, 2 Newton steps (~1e-6 rel)
__device__ __forceinline__ float frsqrt2(float x){
    float y = __int_as_float(0x5f3759df - (__float_as_int(x) >> 1));
    y = y * (1.5f - 0.5f * x * y * y);
    y = y * (1.5f - 0.5f * x * y * y);
    return y;
}

// ---------------- mask dtype probe ----------------
__global__ void detect_mask_kernel(const unsigned char* am){
    unsigned nz = 0;
    #pragma unroll 8
    for (int i = 0; i < 1024; i++) nz |= am[4*i+1] | am[4*i+2] | am[4*i+3];
    g_mask_is_int32 = (nz == 0u) ? 1 : 0;
}

// ---------------- prep Q -> bf16 A-fragment blobs ----------------
__global__ void __launch_bounds__(NTHREADS) prep_qb_kernel(const float* __restrict__ q){
    int w = blockIdx.x * 8 + (threadIdx.x >> 5);
    int lane = threadIdx.x & 31, g = lane >> 2, t = lane & 3;
    int mf = w & 3, ks = (w>>2)&3, ft = (w>>4)&7, qt = (w>>7)&31, b = w>>12;
    unsigned rr[4];
    #pragma unroll
    for (int rh = 0; rh < 2; rh++){
        int row = qt*64 + mf*16 + g + 8*rh;
        const float* qp = q + ((size_t)(b*QQ + row))*FF + ft*64 + ks*16 + 2*t;
        float2 x0 = *(const float2*)qp;
        float2 x1 = *(const float2*)(qp + 8);
        __nv_bfloat162 h0 = __floats2bfloat162_rn(x0.x, x0.y);
        __nv_bfloat162 h1 = __floats2bfloat162_rn(x1.x, x1.y);
        rr[rh]   = *(unsigned*)&h0;
        rr[rh+2] = *(unsigned*)&h1;
    }
    size_t blob = ((size_t)((b*32 + qt)*8 + ft))*2048;
    *(uint4*)(g_Qpb + blob + ((ks*4 + mf)*32 + lane)*4) = make_uint4(rr[0],rr[1],rr[2],rr[3]);
}

// ---------------- prep K -> bf16 B-fragment blobs ----------------
__global__ void __launch_bounds__(NTHREADS) prep_kb_kernel(const float* __restrict__ k){
    int w = blockIdx.x * 8 + (threadIdx.x >> 5);
    int lane = threadIdx.x & 31, g = lane >> 2, t = lane & 3;
    int nf = w & 7, ks = (w>>3)&3, ft = (w>>5)&7, kt = (w>>8)&31, b = w>>13;
    int n = kt*64 + nf*8 + g;
    const float* kp = k + ((size_t)(b*KK2 + n))*FF + ft*64 + ks*16 + 2*t;
    float2 x0 = *(const float2*)kp;
    float2 x1 = *(const float2*)(kp + 8);
    __nv_bfloat162 h0 = __floats2bfloat162_rn(x0.x, x0.y);
    __nv_bfloat162 h1 = __floats2bfloat162_rn(x1.x, x1.y);
    size_t blob = ((size_t)((b*32 + kt)*8 + ft))*2048;
    *(uint2*)(g_Kpb + blob + ((ks*8 + nf)*32 + lane)*2) =
        make_uint2(*(unsigned*)&h0, *(unsigned*)&h1);
}

// ---------------- prep V -> tf32 B-fragment blobs ----------------
__global__ void __launch_bounds__(NTHREADS) prep_v_kernel(const float* __restrict__ v){
    int w = blockIdx.x * 8 + (threadIdx.x >> 5);
    int lane = threadIdx.x & 31, g = lane >> 2, t = lane & 3;
    int nf = w & 7, ks = (w>>3)&7, kt = (w>>6)&31, fvt = (w>>11)&7, b = w>>14;
    unsigned rr[2];
    #pragma unroll
    for (int j = 0; j < 2; j++){
        int kk = kt*64 + ks*8 + t + 4*j;
        int fv = fvt*64 + nf*8 + g;
        rr[j] = to_tf32(v[((size_t)(b*KK2 + kk))*FVV + fv]);
    }
    size_t blob = ((size_t)((b*8 + fvt)*32 + kt))*4096;
    *(uint2*)(g_Vp + blob + ((ks*8 + nf)*32 + lane)*2) = make_uint2(rr[0], rr[1]);
}

// ---------------- pass1 (32-row q-tiles, 2 CTAs/SM): S=QK^T*scale; E=exp(S); linv ----------------
// smQ layout: [ft8][ksmf 8 = ks*2+mf][lane32][4 words]  (only the 2 needed mf blocks per ks)
__global__ void __launch_bounds__(NTHREADS, 2) pass1_kernel(void){
    extern __shared__ unsigned smem_u[];
    unsigned* smQ = smem_u;                    // 8192 words = 32KB
    float* l_s = (float*)(smem_u + 8192);      // 8 warps * 32 rows

    int tid = threadIdx.x, lane = tid & 31, wc = tid >> 5;
    int g = lane >> 2, t = lane & 3;
    int b = blockIdx.x >> 6, qt = blockIdx.x & 63;   // 32-row tile index
    const int qt64 = qt >> 1, mb = (qt & 1) * 2;     // parent 64-row blob, mf base
    const float SCALE = 0.044194173824159216f;       // 1/sqrt(512)

    {   // stage the needed half of each of the 8 Q blobs (32KB total)
        const unsigned* base = g_Qpb + ((size_t)((b*32 + qt64)*8))*2048;
        #pragma unroll
        for (int i = 0; i < 8; i++){
            int j = tid + 256*i;              // [ft][ks][mf][lane]
            int lj = j & 31, mf = (j>>5)&1, ks = (j>>6)&3, ft = j>>8;
            *(uint4*)(smQ + ((size_t)j)*4) =
                *(const uint4*)(base + ft*2048 + ((ks*4 + mb + mf)*32 + lj)*4);
        }
    }
    __syncthreads();

    float rsl[2][2];
    rsl[0][0]=0.f; rsl[0][1]=0.f; rsl[1][0]=0.f; rsl[1][1]=0.f;

    #pragma unroll 1
    for (int kb = 0; kb < 8; kb++){
        int kt = kb*4 + (wc >> 1);
        int nb = (wc & 1) * 4;

        float C[2][4][4];
        #pragma unroll
        for (int a=0;a<2;a++)
            #pragma unroll
            for (int bb=0;bb<4;bb++)
                #pragma unroll
                for (int c=0;c<4;c++) C[a][bb][c]=0.f;

        #pragma unroll 1
        for (int ft = 0; ft < 8; ft++){
            const unsigned* As = smQ + ft*1024;
            const unsigned* Bb = g_Kpb + ((size_t)((b*32 + kt)*8 + ft))*2048;
            #pragma unroll
            for (int ks = 0; ks < 4; ks++){
                uint4 Af[2];
                #pragma unroll
                for (int mf=0; mf<2; mf++)
                    Af[mf] = *(const uint4*)(As + ((ks*2 + mf)*32 + lane)*4);
                uint2 Bf[4];
                #pragma unroll
                for (int nf=0; nf<4; nf++)
                    Bf[nf] = *(const uint2*)(Bb + ((ks*8 + nb + nf)*32 + lane)*2);
                #pragma unroll
                for (int mf=0; mf<2; mf++)
                    #pragma unroll
                    for (int nf=0; nf<4; nf++)
                        mma_bf16(C[mf][nf], (const unsigned*)&Af[mf], (const unsigned*)&Bf[nf]);
            }
        }

        // exp + E store + row-sum partials
        #pragma unroll
        for (int mf = 0; mf < 2; mf++)
            #pragma unroll
            for (int rh = 0; rh < 2; rh++){
                int row = qt*32 + mf*16 + g + 8*rh;
                float rs = 0.f;
                #pragma unroll
                for (int nf = 0; nf < 4; nf++){
                    float e0 = fexp(C[mf][nf][rh*2+0] * SCALE);
                    float e1 = fexp(C[mf][nf][rh*2+1] * SCALE);
                    rs += e0 + e1;
                    int kcol = kb*256 + wc*32 + nf*8 + 2*t;
                    size_t idx = ((size_t)(b*QQ + row))*KK2 + kcol;
                    ((__nv_bfloat162*)g_E)[idx >> 1] = __floats2bfloat162_rn(e0, e1);
                }
                rsl[mf][rh] += rs;
            }
    }

    #pragma unroll
    for (int mf = 0; mf < 2; mf++)
        #pragma unroll
        for (int rh = 0; rh < 2; rh++){
            float rs = rsl[mf][rh];
            rs += __shfl_xor_sync(0xffffffffu, rs, 1);
            rs += __shfl_xor_sync(0xffffffffu, rs, 2);
            if (t == 0) l_s[wc*32 + mf*16 + g + 8*rh] = rs;
        }
    __syncthreads();
    if (tid < 32){
        float s = 0.f;
        #pragma unroll
        for (int w = 0; w < 8; w++) s += l_s[w*32 + tid];
        g_linv[b*QQ + qt*32 + tid] = 1.0f / s;
    }
}

// ---------------- pass2 (fused, 32-row q-tiles, 2 CTAs/SM): W in smem; O = W*V ----------------
#define WPAD 68
__global__ void __launch_bounds__(NTHREADS, 2) pass2_kernel(
    float* __restrict__ out,
    const float* __restrict__ cq, const float* __restrict__ ck,
    const unsigned char* __restrict__ am, const unsigned char* __restrict__ al,
    const float* __restrict__ bias)
{
    extern __shared__ float smem[];   // 2 * 32*68 floats = 17408 B
    int tid = threadIdx.x, lane = tid & 31, wc = tid >> 5;
    int g = lane >> 2, t = lane & 3;
    int b = blockIdx.x >> 6, qt = blockIdx.x & 63;
    const int q0 = qt*32;

    // build role: thread owns row brow (0..31), 8 cols at bc0 (within 64-col k-tile)
    const int brow = tid >> 3;
    const int bc0  = (tid & 7) * 8;
    const float2 cqv = *(const float2*)(cq + ((size_t)(b*QQ + q0 + brow))*2);
    const float li   = g_linv[b*QQ + q0 + brow];
    const size_t erow = ((size_t)(b*QQ + q0 + brow))*KK2;
    const float bsc = __ldg(bias);
    const int m32 = g_mask_is_int32;

    float C[2][8][4];
    #pragma unroll
    for (int a=0;a<2;a++)
        #pragma unroll
        for (int n=0;n<8;n++)
            #pragma unroll
            for (int c=0;c<4;c++) C[a][n][c]=0.f;

    #pragma unroll 1
    for (int kt = 0; kt < 32; kt++){
        float* Wb = smem + (kt & 1) * (32*WPAD);

        // ---- build W tile (32x64): 8 elems per thread ----
        {
            int cb = kt*64 + bc0;
            uint4 eu = *(const uint4*)(g_E + erow + cb);       // 8 bf16
            const unsigned* ew = (const unsigned*)&eu;
            int amv[8], alv[8];
            if (m32){
                const int4* ap = (const int4*)((const int*)am + erow + cb);
                const int4* lp = (const int4*)((const int*)al + erow + cb);
                int4 a0 = ap[0], a1 = ap[1], l0 = lp[0], l1 = lp[1];
                amv[0]=a0.x; amv[1]=a0.y; amv[2]=a0.z; amv[3]=a0.w;
                amv[4]=a1.x; amv[5]=a1.y; amv[6]=a1.z; amv[7]=a1.w;
                alv[0]=l0.x; alv[1]=l0.y; alv[2]=l0.z; alv[3]=l0.w;
                alv[4]=l1.x; alv[5]=l1.y; alv[6]=l1.z; alv[7]=l1.w;
            } else {
                uint2 au = *(const uint2*)(am + erow + cb);
                uint2 lu = *(const uint2*)(al + erow + cb);
                const unsigned char* ab = (const unsigned char*)&au;
                const unsigned char* lb = (const unsigned char*)&lu;
                #pragma unroll
                for (int c = 0; c < 8; c++){ amv[c] = ab[c]; alv[c] = lb[c]; }
            }
            float4 ck4[4];
            #pragma unroll
            for (int i = 0; i < 4; i++)
                ck4[i] = __ldg((const float4*)(ck + ((size_t)(b*KK2 + cb))*2) + i);
            const float2* ckp = (const float2*)&ck4[0];

            float wv[8];
            #pragma unroll
            for (int c = 0; c < 8; c++){
                __nv_bfloat162 e2 = *(__nv_bfloat162*)&ew[c>>1];
                float e = __bfloat162float((c & 1) ? e2.y : e2.x) * li;
                float dx = cqv.x - ckp[c].x;
                float dy = cqv.y - ckp[c].y;
                float r2 = fmaxf(dx*dx + dy*dy, 1e-30f);
                float d  = alv[c] ? 0.f : (r2 * frsqrt2(r2) * bsc);
                float w  = amv[c] ? 0.f : (e - d);
                wv[c] = __uint_as_float(to_tf32(w));
            }
            float* wd = Wb + brow*WPAD + bc0;
            *(float4*)(wd)     = make_float4(wv[0], wv[1], wv[2], wv[3]);
            *(float4*)(wd + 4) = make_float4(wv[4], wv[5], wv[6], wv[7]);
        }
        __syncthreads();

        // ---- mma: A frags from Wb (4x LDS.32, conflict-free), B from g_Vp ----
        const float* Bb = g_Vp + ((size_t)((b*8 + wc)*32 + kt))*4096;
        #pragma unroll
        for (int ks = 0; ks < 8; ks++){
            unsigned Af[2][4];
            #pragma unroll
            for (int mf = 0; mf < 2; mf++){
                #pragma unroll
                for (int r = 0; r < 4; r++){
                    int row = mf*16 + g + 8*(r & 1);
                    int col = ks*8 + t + 4*(r >> 1);
                    Af[mf][r] = __float_as_uint(Wb[row*WPAD + col]);
                }
            }
            uint2 Bf[8];
            #pragma unroll
            for (int nf = 0; nf < 8; nf++)
                Bf[nf] = *(const uint2*)(Bb + ((ks*8 + nf)*32 + lane)*2);
            #pragma unroll
            for (int mf = 0; mf < 2; mf++)
                #pragma unroll
                for (int nf = 0; nf < 8; nf++)
                    mma_tf32(C[mf][nf], Af[mf], (const unsigned*)&Bf[nf]);
        }
        // next build writes the other buffer; sync(kt+1) transitively orders
        // mma(kt) readers before build(kt+2) rewrites this buffer.
    }

    // ---- epilogue ----
    #pragma unroll
    for (int mf = 0; mf < 2; mf++)
        #pragma unroll
        for (int rh = 0; rh < 2; rh++){
            int row = q0 + mf*16 + g + 8*rh;
            float* orow = out + ((size_t)(b*QQ + row))*FVV;
            #pragma unroll
            for (int nf = 0; nf < 8; nf++){
                int fv = wc*64 + nf*8 + 2*t;
                *(float2*)(orow + fv) = make_float2(C[mf][nf][rh*2+0], C[mf][nf][rh*2+1]);
            }
        }
}

extern "C" void kernel_launch(void* const* d_in, const int* in_sizes, int n_in,
                              void* d_out, int out_size)
{
    const float*         q    = (const float*)d_in[0];
    const float*         k    = (const float*)d_in[1];
    const float*         v    = (const float*)d_in[2];
    const float*         cq   = (const float*)d_in[3];
    const float*         ck   = (const float*)d_in[4];
    const unsigned char* am   = (const unsigned char*)d_in[5];
    const unsigned char* al   = (const unsigned char*)d_in[6];
    const float*         bias = (const float*)d_in[7];
    float*               out  = (float*)d_out;

    static int smem_set = 0;
    if (!smem_set){
        cudaFuncSetAttribute(pass1_kernel, cudaFuncAttributeMaxDynamicSharedMemorySize, 33792);
        cudaFuncSetAttribute(pass2_kernel, cudaFuncAttributeMaxDynamicSharedMemorySize, 17408);
        smem_set = 1;
    }

    detect_mask_kernel<<<1, 1>>>(am);
    prep_qb_kernel<<<4096,  NTHREADS>>>(q);
    prep_kb_kernel<<<8192,  NTHREADS>>>(k);
    prep_v_kernel <<<16384, NTHREADS>>>(v);
    pass1_kernel<<<512, NTHREADS, 33792>>>();
    pass2_kernel<<<512, NTHREADS, 17408>>>(out, cq, ck, am, al, bias);
}

// round 12
// speedup vs baseline: 1.6994x; 1.2695x over previous
#include <cuda_runtime.h>
#include <cuda_bf16.h>
#include <cuda_fp16.h>
#include <math.h>

#define BB   8
#define QQ   2048
#define KK2  2048
#define FF   512
#define FVV  512
#define NTHREADS 256

// ---------------- scratch (device globals; no runtime allocation) ----------------
// bf16 A-blob (64x64): [ks4][mf4][lane32][4 b32]
// bf16/fp16 B-blob (64k x 64n): [ks4][nf8][lane32][2 b32]; w0=(k=16ks+2t,2t+1 | n), w1=(+8,+9 | n)
__device__ __align__(16) unsigned g_Qpb[4194304];     // (b, qt32, ft8) bf16 A-blobs   16.8MB
__device__ __align__(16) unsigned g_Kpb[4194304];     // (b, kt32, ft8) bf16 B-blobs   16.8MB
__device__ __align__(16) unsigned g_Vph[4194304];     // (b, fvt8, kt32) fp16 B-blobs  16.8MB
__device__ __align__(16) __nv_bfloat16 g_E[33554432]; // exp(logits) row-major         67MB
__device__ float g_linv[BB*QQ];
__device__ int   g_mask_is_int32;

// ---------------- helpers ----------------
__device__ __forceinline__ void mma_bf16(float c[4], const unsigned* a, const unsigned* b){
    asm volatile("mma.sync.aligned.m16n8k16.row.col.f32.bf16.bf16.f32 "
        "{%0,%1,%2,%3}, {%4,%5,%6,%7}, {%8,%9}, {%0,%1,%2,%3};"
        : "+f"(c[0]), "+f"(c[1]), "+f"(c[2]), "+f"(c[3])
        : "r"(a[0]), "r"(a[1]), "r"(a[2]), "r"(a[3]), "r"(b[0]), "r"(b[1]));
}
__device__ __forceinline__ void mma_fp16(float c[4], const unsigned* a, const unsigned* b){
    asm volatile("mma.sync.aligned.m16n8k16.row.col.f32.f16.f16.f32 "
        "{%0,%1,%2,%3}, {%4,%5,%6,%7}, {%8,%9}, {%0,%1,%2,%3};"
        : "+f"(c[0]), "+f"(c[1]), "+f"(c[2]), "+f"(c[3])
        : "r"(a[0]), "r"(a[1]), "r"(a[2]), "r"(a[3]), "r"(b[0]), "r"(b[1]));
}
// exp on the FMA pipe: 2^(x*log2e), deg-5 poly (rel err ~2e-7 for |x| < 15)
__device__ __forceinline__ float fexp(float x){
    float t = x * 1.4426950408889634f;
    float r = rintf(t);
    float f = t - r;
    float p = 1.3333558146428443e-3f;
    p = fmaf(p, f, 9.618129107628477e-3f);
    p = fmaf(p, f, 5.550410866482158e-2f);
    p = fmaf(p, f, 2.402265069591007e-1f);
    p = fmaf(p, f, 6.931471805599453e-1f);
    p = fmaf(p, f, 1.0f);
    return __int_as_float(((int)r + 127) << 23) * p;
}
// rsqrt on FMA pipe, 2 Newton steps (~1e-6 rel)
__device__ __forceinline__ float frsqrt2(float x){
    float y = __int_as_float(0x5f3759df - (__float_as_int(x) >> 1));
    y = y * (1.5f - 0.5f * x * y * y);
    y = y * (1.5f - 0.5f * x * y * y);
    return y;
}

// ---------------- mask dtype probe ----------------
__global__ void detect_mask_kernel(const unsigned char* am){
    unsigned nz = 0;
    #pragma unroll 8
    for (int i = 0; i < 1024; i++) nz |= am[4*i+1] | am[4*i+2] | am[4*i+3];
    g_mask_is_int32 = (nz == 0u) ? 1 : 0;
}

// ---------------- prep Q -> bf16 A-fragment blobs ----------------
__global__ void __launch_bounds__(NTHREADS) prep_qb_kernel(const float* __restrict__ q){
    int w = blockIdx.x * 8 + (threadIdx.x >> 5);
    int lane = threadIdx.x & 31, g = lane >> 2, t = lane & 3;
    int mf = w & 3, ks = (w>>2)&3, ft = (w>>4)&7, qt = (w>>7)&31, b = w>>12;
    unsigned rr[4];
    #pragma unroll
    for (int rh = 0; rh < 2; rh++){
        int row = qt*64 + mf*16 + g + 8*rh;
        const float* qp = q + ((size_t)(b*QQ + row))*FF + ft*64 + ks*16 + 2*t;
        float2 x0 = *(const float2*)qp;
        float2 x1 = *(const float2*)(qp + 8);
        __nv_bfloat162 h0 = __floats2bfloat162_rn(x0.x, x0.y);
        __nv_bfloat162 h1 = __floats2bfloat162_rn(x1.x, x1.y);
        rr[rh]   = *(unsigned*)&h0;
        rr[rh+2] = *(unsigned*)&h1;
    }
    size_t blob = ((size_t)((b*32 + qt)*8 + ft))*2048;
    *(uint4*)(g_Qpb + blob + ((ks*4 + mf)*32 + lane)*4) = make_uint4(rr[0],rr[1],rr[2],rr[3]);
}

// ---------------- prep K -> bf16 B-fragment blobs ----------------
__global__ void __launch_bounds__(NTHREADS) prep_kb_kernel(const float* __restrict__ k){
    int w = blockIdx.x * 8 + (threadIdx.x >> 5);
    int lane = threadIdx.x & 31, g = lane >> 2, t = lane & 3;
    int nf = w & 7, ks = (w>>3)&3, ft = (w>>5)&7, kt = (w>>8)&31, b = w>>13;
    int n = kt*64 + nf*8 + g;
    const float* kp = k + ((size_t)(b*KK2 + n))*FF + ft*64 + ks*16 + 2*t;
    float2 x0 = *(const float2*)kp;
    float2 x1 = *(const float2*)(kp + 8);
    __nv_bfloat162 h0 = __floats2bfloat162_rn(x0.x, x0.y);
    __nv_bfloat162 h1 = __floats2bfloat162_rn(x1.x, x1.y);
    size_t blob = ((size_t)((b*32 + kt)*8 + ft))*2048;
    *(uint2*)(g_Kpb + blob + ((ks*8 + nf)*32 + lane)*2) =
        make_uint2(*(unsigned*)&h0, *(unsigned*)&h1);
}

// ---------------- prep V -> fp16 B-fragment blobs (smem transpose, coalesced) ----------------
// blob (b, fvt, kt): contraction k = seq (64), n = fv (64).
__global__ void __launch_bounds__(NTHREADS) prep_vh_kernel(const float* __restrict__ v){
    __shared__ float ts[64][68];
    int bx = blockIdx.x;                 // 8 fb x 32 kt x 8 b
    int fb = bx & 7, kt = (bx>>3) & 31, b = bx >> 8;
    int tid = threadIdx.x;
    {   // load 64 seq-rows x 64 fv cols, float4-coalesced
        int fc = (tid & 15) * 4;
        int k0 = tid >> 4;
        #pragma unroll
        for (int it = 0; it < 4; it++){
            int kk = it*16 + k0;
            float4 x = *(const float4*)(v + ((size_t)(b*KK2 + kt*64 + kk))*FVV + fb*64 + fc);
            *(float4*)&ts[kk][fc] = x;
        }
    }
    __syncthreads();
    int lane = tid & 31, g = lane >> 2, t = lane & 3;
    int nf = tid >> 5;
    int n = nf*8 + g;
    unsigned* dst = g_Vph + ((size_t)((b*8 + fb)*32 + kt))*2048;
    #pragma unroll
    for (int ks = 0; ks < 4; ks++){
        __half2 w0 = __floats2half2_rn(ts[ks*16 + 2*t    ][n], ts[ks*16 + 2*t + 1][n]);
        __half2 w1 = __floats2half2_rn(ts[ks*16 + 2*t + 8][n], ts[ks*16 + 2*t + 9][n]);
        *(uint2*)(dst + ((ks*8 + nf)*32 + lane)*2) =
            make_uint2(*(unsigned*)&w0, *(unsigned*)&w1);
    }
}

// ---------------- pass1 (32-row q-tiles, 2 CTAs/SM): S=QK^T*scale; E=exp(S); linv ----------------
__global__ void __launch_bounds__(NTHREADS, 2) pass1_kernel(void){
    extern __shared__ unsigned smem_u[];
    unsigned* smQ = smem_u;                    // 8192 words = 32KB
    float* l_s = (float*)(smem_u + 8192);      // 8 warps * 32 rows

    int tid = threadIdx.x, lane = tid & 31, wc = tid >> 5;
    int g = lane >> 2, t = lane & 3;
    int b = blockIdx.x >> 6, qt = blockIdx.x & 63;
    const int qt64 = qt >> 1, mb = (qt & 1) * 2;
    const float SCALE = 0.044194173824159216f;  // 1/sqrt(512)

    {
        const unsigned* base = g_Qpb + ((size_t)((b*32 + qt64)*8))*2048;
        #pragma unroll
        for (int i = 0; i < 8; i++){
            int j = tid + 256*i;
            int lj = j & 31, mf = (j>>5)&1, ks = (j>>6)&3, ft = j>>8;
            *(uint4*)(smQ + ((size_t)j)*4) =
                *(const uint4*)(base + ft*2048 + ((ks*4 + mb + mf)*32 + lj)*4);
        }
    }
    __syncthreads();

    float rsl[2][2];
    rsl[0][0]=0.f; rsl[0][1]=0.f; rsl[1][0]=0.f; rsl[1][1]=0.f;

    #pragma unroll 1
    for (int kb = 0; kb < 8; kb++){
        int kt = kb*4 + (wc >> 1);
        int nb = (wc & 1) * 4;

        float C[2][4][4];
        #pragma unroll
        for (int a=0;a<2;a++)
            #pragma unroll
            for (int bb=0;bb<4;bb++)
                #pragma unroll
                for (int c=0;c<4;c++) C[a][bb][c]=0.f;

        #pragma unroll 1
        for (int ft = 0; ft < 8; ft++){
            const unsigned* As = smQ + ft*1024;
            const unsigned* Bb = g_Kpb + ((size_t)((b*32 + kt)*8 + ft))*2048;
            #pragma unroll
            for (int ks = 0; ks < 4; ks++){
                uint4 Af[2];
                #pragma unroll
                for (int mf=0; mf<2; mf++)
                    Af[mf] = *(const uint4*)(As + ((ks*2 + mf)*32 + lane)*4);
                uint2 Bf[4];
                #pragma unroll
                for (int nf=0; nf<4; nf++)
                    Bf[nf] = *(const uint2*)(Bb + ((ks*8 + nb + nf)*32 + lane)*2);
                #pragma unroll
                for (int mf=0; mf<2; mf++)
                    #pragma unroll
                    for (int nf=0; nf<4; nf++)
                        mma_bf16(C[mf][nf], (const unsigned*)&Af[mf], (const unsigned*)&Bf[nf]);
            }
        }

        #pragma unroll
        for (int mf = 0; mf < 2; mf++)
            #pragma unroll
            for (int rh = 0; rh < 2; rh++){
                int row = qt*32 + mf*16 + g + 8*rh;
                float rs = 0.f;
                #pragma unroll
                for (int nf = 0; nf < 4; nf++){
                    float e0 = fexp(C[mf][nf][rh*2+0] * SCALE);
                    float e1 = fexp(C[mf][nf][rh*2+1] * SCALE);
                    rs += e0 + e1;
                    int kcol = kb*256 + wc*32 + nf*8 + 2*t;
                    size_t idx = ((size_t)(b*QQ + row))*KK2 + kcol;
                    ((__nv_bfloat162*)g_E)[idx >> 1] = __floats2bfloat162_rn(e0, e1);
                }
                rsl[mf][rh] += rs;
            }
    }

    #pragma unroll
    for (int mf = 0; mf < 2; mf++)
        #pragma unroll
        for (int rh = 0; rh < 2; rh++){
            float rs = rsl[mf][rh];
            rs += __shfl_xor_sync(0xffffffffu, rs, 1);
            rs += __shfl_xor_sync(0xffffffffu, rs, 2);
            if (t == 0) l_s[wc*32 + mf*16 + g + 8*rh] = rs;
        }
    __syncthreads();
    if (tid < 32){
        float s = 0.f;
        #pragma unroll
        for (int w = 0; w < 8; w++) s += l_s[w*32 + tid];
        g_linv[b*QQ + qt*32 + tid] = 1.0f / s;
    }
}

// ---------------- pass2 (fused, fp16 mma, 32-row q-tiles, 2 CTAs/SM): W in smem; O = W*V ----------------
// W smem: double-buffered 32 rows x 72 halves (144B row stride). A-frag LDS.32 bank-conflict-free:
// word = row*36 + ks*8 + t + 4*hi -> bank (4g + t + c) mod 32, distinct per warp.
#define WROW 36   // row stride in 32-bit words
__global__ void __launch_bounds__(NTHREADS, 2) pass2_kernel(
    float* __restrict__ out,
    const float* __restrict__ cq, const float* __restrict__ ck,
    const unsigned char* __restrict__ am, const unsigned char* __restrict__ al,
    const float* __restrict__ bias)
{
    extern __shared__ unsigned smw[];   // 2 * 32*36 words = 9216 B
    int tid = threadIdx.x, lane = tid & 31, wc = tid >> 5;
    int g = lane >> 2, t = lane & 3;
    int b = blockIdx.x >> 6, qt = blockIdx.x & 63;
    const int q0 = qt*32;

    // build role: thread owns row brow (0..31), 8 cols at bc0 (within 64-col k-tile)
    const int brow = tid >> 3;
    const int bc0  = (tid & 7) * 8;
    const float2 cqv = *(const float2*)(cq + ((size_t)(b*QQ + q0 + brow))*2);
    const float li   = g_linv[b*QQ + q0 + brow];
    const size_t erow = ((size_t)(b*QQ + q0 + brow))*KK2;
    const float bsc = __ldg(bias);
    const int m32 = g_mask_is_int32;

    float C[2][8][4];
    #pragma unroll
    for (int a=0;a<2;a++)
        #pragma unroll
        for (int n=0;n<8;n++)
            #pragma unroll
            for (int c=0;c<4;c++) C[a][n][c]=0.f;

    #pragma unroll 1
    for (int kt = 0; kt < 32; kt++){
        unsigned* Wb = smw + (kt & 1) * (32*WROW);

        // ---- build W tile (32x64 fp16): 8 elems per thread ----
        {
            int cb = kt*64 + bc0;
            uint4 eu = *(const uint4*)(g_E + erow + cb);       // 8 bf16
            const unsigned* ew = (const unsigned*)&eu;
            int amv[8], alv[8];
            if (m32){
                const int4* ap = (const int4*)((const int*)am + erow + cb);
                const int4* lp = (const int4*)((const int*)al + erow + cb);
                int4 a0 = ap[0], a1 = ap[1], l0 = lp[0], l1 = lp[1];
                amv[0]=a0.x; amv[1]=a0.y; amv[2]=a0.z; amv[3]=a0.w;
                amv[4]=a1.x; amv[5]=a1.y; amv[6]=a1.z; amv[7]=a1.w;
                alv[0]=l0.x; alv[1]=l0.y; alv[2]=l0.z; alv[3]=l0.w;
                alv[4]=l1.x; alv[5]=l1.y; alv[6]=l1.z; alv[7]=l1.w;
            } else {
                uint2 au = *(const uint2*)(am + erow + cb);
                uint2 lu = *(const uint2*)(al + erow + cb);
                const unsigned char* ab = (const unsigned char*)&au;
                const unsigned char* lb = (const unsigned char*)&lu;
                #pragma unroll
                for (int c = 0; c < 8; c++){ amv[c] = ab[c]; alv[c] = lb[c]; }
            }
            float4 ck4[4];
            #pragma unroll
            for (int i = 0; i < 4; i++)
                ck4[i] = __ldg((const float4*)(ck + ((size_t)(b*KK2 + cb))*2) + i);
            const float2* ckp = (const float2*)&ck4[0];

            float wv[8];
            #pragma unroll
            for (int c = 0; c < 8; c++){
                __nv_bfloat162 e2 = *(__nv_bfloat162*)&ew[c>>1];
                float e = __bfloat162float((c & 1) ? e2.y : e2.x) * li;
                float dx = cqv.x - ckp[c].x;
                float dy = cqv.y - ckp[c].y;
                float r2 = fmaxf(dx*dx + dy*dy, 1e-30f);
                float d  = alv[c] ? 0.f : (r2 * frsqrt2(r2) * bsc);
                wv[c] = amv[c] ? 0.f : (e - d);
            }
            __half2 h0 = __floats2half2_rn(wv[0], wv[1]);
            __half2 h1 = __floats2half2_rn(wv[2], wv[3]);
            __half2 h2 = __floats2half2_rn(wv[4], wv[5]);
            __half2 h3 = __floats2half2_rn(wv[6], wv[7]);
            *(uint4*)(Wb + brow*WROW + (tid & 7)*4) =
                make_uint4(*(unsigned*)&h0, *(unsigned*)&h1, *(unsigned*)&h2, *(unsigned*)&h3);
        }
        __syncthreads();

        // ---- mma fp16: A frags from Wb (4x LDS.32, conflict-free), B from g_Vph ----
        const unsigned* Bb = g_Vph + ((size_t)((b*8 + wc)*32 + kt))*2048;
        #pragma unroll
        for (int ks = 0; ks < 4; ks++){
            unsigned Af[2][4];
            #pragma unroll
            for (int mf = 0; mf < 2; mf++){
                int rowbase = (mf*16 + g)*WROW + ks*8 + t;
                Af[mf][0] = Wb[rowbase];
                Af[mf][1] = Wb[rowbase + 8*WROW];
                Af[mf][2] = Wb[rowbase + 4];
                Af[mf][3] = Wb[rowbase + 8*WROW + 4];
            }
            uint2 Bf[8];
            #pragma unroll
            for (int nf = 0; nf < 8; nf++)
                Bf[nf] = *(const uint2*)(Bb + ((ks*8 + nf)*32 + lane)*2);
            #pragma unroll
            for (int mf = 0; mf < 2; mf++)
                #pragma unroll
                for (int nf = 0; nf < 8; nf++)
                    mma_fp16(C[mf][nf], Af[mf], (const unsigned*)&Bf[nf]);
        }
        // next build writes the other buffer; sync(kt+1) transitively orders
        // mma(kt) readers before build(kt+2) rewrites this buffer.
    }

    // ---- epilogue ----
    #pragma unroll
    for (int mf = 0; mf < 2; mf++)
        #pragma unroll
        for (int rh = 0; rh < 2; rh++){
            int row = q0 + mf*16 + g + 8*rh;
            float* orow = out + ((size_t)(b*QQ + row))*FVV;
            #pragma unroll
            for (int nf = 0; nf < 8; nf++){
                int fv = wc*64 + nf*8 + 2*t;
                *(float2*)(orow + fv) = make_float2(C[mf][nf][rh*2+0], C[mf][nf][rh*2+1]);
            }
        }
}

extern "C" void kernel_launch(void* const* d_in, const int* in_sizes, int n_in,
                              void* d_out, int out_size)
{
    const float*         q    = (const float*)d_in[0];
    const float*         k    = (const float*)d_in[1];
    const float*         v    = (const float*)d_in[2];
    const float*         cq   = (const float*)d_in[3];
    const float*         ck   = (const float*)d_in[4];
    const unsigned char* am   = (const unsigned char*)d_in[5];
    const unsigned char* al   = (const unsigned char*)d_in[6];
    const float*         bias = (const float*)d_in[7];
    float*               out  = (float*)d_out;

    static int smem_set = 0;
    if (!smem_set){
        cudaFuncSetAttribute(pass1_kernel, cudaFuncAttributeMaxDynamicSharedMemorySize, 33792);
        cudaFuncSetAttribute(pass2_kernel, cudaFuncAttributeMaxDynamicSharedMemorySize, 9216);
        smem_set = 1;
    }

    detect_mask_kernel<<<1, 1>>>(am);
    prep_qb_kernel<<<4096, NTHREADS>>>(q);
    prep_kb_kernel<<<8192, NTHREADS>>>(k);
    prep_vh_kernel<<<2048, NTHREADS>>>(v);
    pass1_kernel<<<512, NTHREADS, 33792>>>();
    pass2_kernel<<<512, NTHREADS, 9216>>>(out, cq, ck, am, al, bias);
}